// round 2
// baseline (speedup 1.0000x reference)
#include <cuda_runtime.h>
#include <math.h>

#define CIN  256
#define COUT 256
#define HH   64
#define WW   64
#define BB   4
#define DGRP 2
#define CG   128
#define KK2  9
#define NTAP 18
#define NPIX 4096   // 64*64

// ---------------- scratch (device globals; no allocations allowed) ----------------
__device__ float g_xt[BB * NPIX * CIN];        // x transposed to [B][H*W][C]   (16.8 MB)
__device__ float g_wt[COUT * NTAP * CG];       // w  -> [o][tap][c]             (2.36 MB)
__device__ float g_wofft[KK2 * CIN * 56];      // w_off -> [k2][ci][oc(pad 56)] (516 KB)
__device__ float g_om[BB * NPIX * 54];         // raw offset-conv output [b][p][54]

// ---------------- packed f32x2 helpers ----------------
static __device__ __forceinline__ unsigned long long pack2(float a, float b) {
    unsigned long long r;
    asm("mov.b64 %0, {%1, %2};" : "=l"(r) : "f"(a), "f"(b));
    return r;
}
static __device__ __forceinline__ void unpack2(unsigned long long v, float& a, float& b) {
    asm("mov.b64 {%0, %1}, %2;" : "=f"(a), "=f"(b) : "l"(v));
}
static __device__ __forceinline__ unsigned long long ffma2(
    unsigned long long a, unsigned long long b, unsigned long long c) {
    unsigned long long d;
    asm("fma.rn.f32x2 %0, %1, %2, %3;" : "=l"(d) : "l"(a), "l"(b), "l"(c));
    return d;
}

// ---------------- kernel 0: x [B,C,H,W] -> g_xt [B,HW,C] ----------------
__global__ void k_transpose_x(const float* __restrict__ x) {
    __shared__ float tile[32][33];
    int b  = blockIdx.z;
    int p0 = blockIdx.x * 32;   // pixel tile
    int c0 = blockIdx.y * 32;   // channel tile
    #pragma unroll
    for (int k = 0; k < 32; k += 8) {
        int c = c0 + threadIdx.y + k;
        int p = p0 + threadIdx.x;
        tile[threadIdx.y + k][threadIdx.x] = x[(b * CIN + c) * NPIX + p];
    }
    __syncthreads();
    #pragma unroll
    for (int k = 0; k < 32; k += 8) {
        int p = p0 + threadIdx.y + k;
        int c = c0 + threadIdx.x;
        g_xt[(b * NPIX + p) * CIN + c] = tile[threadIdx.x][threadIdx.y + k];
    }
}

// ---------------- kernel 1: w [O,C,3,3] -> g_wt [o][tap][c] ----------------
__global__ void k_transpose_w(const float* __restrict__ w) {
    int tid = blockIdx.x * blockDim.x + threadIdx.x;
    if (tid >= COUT * NTAP * CG) return;
    int c   = tid & (CG - 1);
    int tap = (tid >> 7) % NTAP;
    int o   = tid / (NTAP * CG);
    int g   = tap / KK2, k2 = tap % KK2;
    g_wt[tid] = w[(o * CIN + g * CG + c) * KK2 + k2];
}

// ---------------- kernel 2: w_off [54,C,3,3] -> g_wofft [k2][ci][oc pad 56] ----------------
__global__ void k_transpose_woff(const float* __restrict__ w_off) {
    int tid = blockIdx.x * blockDim.x + threadIdx.x;
    if (tid >= KK2 * CIN * 56) return;
    int oc = tid % 56;
    int ci = (tid / 56) % CIN;
    int k2 = tid / (56 * CIN);
    g_wofft[tid] = (oc < 54) ? w_off[(oc * CIN + ci) * KK2 + k2] : 0.f;
}

// ---------------- kernel 3: offset conv (54 ch, f32x2-packed direct conv) ----------------
__global__ void __launch_bounds__(128) k_offset_conv(const float* __restrict__ b_off) {
    __shared__ __align__(16) float ws[128 * 56];   // [c_local][oc pad 56]
    int b = blockIdx.x >> 5;
    int p = ((blockIdx.x & 31) << 7) + threadIdx.x;  // 128 pixels per block
    int h = p >> 6, wx = p & 63;

    unsigned long long acc[28];
    #pragma unroll
    for (int j = 0; j < 28; j++) acc[j] = 0ull;

    for (int k2 = 0; k2 < KK2; k2++) {
        int kyi = k2 / 3, kxi = k2 % 3;
        int y = h + kyi - 1, x_ = wx + kxi - 1;
        bool valid = (y >= 0) && (y < HH) && (x_ >= 0) && (x_ < WW);
        const float4* xrow = (const float4*)&g_xt[(b * NPIX + (valid ? (y * WW + x_) : 0)) * CIN];

        for (int half = 0; half < 2; half++) {
            __syncthreads();
            // stage 128x56 weight slab (contiguous copy from transposed layout)
            {
                const float4* src = (const float4*)&g_wofft[(k2 * CIN + half * 128) * 56];
                float4* dst = (float4*)ws;
                for (int e = threadIdx.x; e < 128 * 56 / 4; e += 128) dst[e] = src[e];
            }
            __syncthreads();
            if (valid) {
                #pragma unroll 1
                for (int c4 = 0; c4 < 32; c4++) {
                    float4 xv = xrow[half * 32 + c4];
                    #pragma unroll
                    for (int u = 0; u < 4; u++) {
                        float xc = (&xv.x)[u];
                        unsigned long long xp = pack2(xc, xc);
                        const ulonglong2* wr = (const ulonglong2*)&ws[(c4 * 4 + u) * 56];
                        #pragma unroll
                        for (int j2 = 0; j2 < 14; j2++) {
                            ulonglong2 wv = wr[j2];
                            acc[2 * j2]     = ffma2(xp, wv.x, acc[2 * j2]);
                            acc[2 * j2 + 1] = ffma2(xp, wv.y, acc[2 * j2 + 1]);
                        }
                    }
                }
            }
        }
    }
    float* orow = &g_om[(b * NPIX + p) * 54];
    #pragma unroll
    for (int j = 0; j < 27; j++) {
        float a0, a1;
        unpack2(acc[j], a0, a1);
        orow[2 * j]     = a0 + b_off[2 * j];
        orow[2 * j + 1] = a1 + b_off[2 * j + 1];
    }
}

// ---------------- kernel 4: deformable conv + BN + ReLU ----------------
// block: 256 threads (one output channel each), 32 consecutive pixels (one half-row)
__global__ void __launch_bounds__(256) k_main(
    const float* __restrict__ bconv, const float* __restrict__ gamma,
    const float* __restrict__ beta,  const float* __restrict__ rmean,
    const float* __restrict__ rvar,  float* __restrict__ out) {

    __shared__ __align__(16) float s[128 * 36];   // sampled A-tile: [c][pix pad 36]
    __shared__ float cw[32][4];                   // bilinear weights * mask (per pixel/corner)
    __shared__ int   ci[32][4];                   // corner base offsets into g_xt (incl. group)

    int b  = blockIdx.x >> 7;
    int p0 = (blockIdx.x & 127) << 5;             // 32 pixels, same row
    int o    = threadIdx.x;
    int lane = threadIdx.x & 31, wid = threadIdx.x >> 5;

    unsigned long long acc[16];
    #pragma unroll
    for (int j = 0; j < 16; j++) acc[j] = 0ull;

    const float* xb  = &g_xt[b * NPIX * CIN];
    const float* omb = &g_om[b * NPIX * 54];

    for (int tap = 0; tap < NTAP; tap++) {
        int g = tap / KK2, k2 = tap % KK2;
        __syncthreads();  // protect s/cw from previous tap's readers
        if (threadIdx.x < 32) {
            int p = p0 + threadIdx.x;
            int h = p >> 6, wx = p & 63;
            const float* om = &omb[p * 54 + tap];
            float offy = om[0], offx = om[18], mraw = om[36];
            float mask = 1.f / (1.f + expf(-mraw));
            float py = (float)(h + k2 / 3 - 1) + offy;
            float px = (float)(wx + k2 % 3 - 1) + offx;
            float fy = floorf(py), fx = floorf(px);
            float ly = py - fy, lx = px - fx;
            int y0 = (int)fy, x0 = (int)fx;
            float wgt[4] = { (1.f - ly) * (1.f - lx), (1.f - ly) * lx,
                             ly * (1.f - lx),         ly * lx };
            #pragma unroll
            for (int cr = 0; cr < 4; cr++) {
                int yy = y0 + (cr >> 1), xx = x0 + (cr & 1);
                bool v = (yy >= 0) && (yy < HH) && (xx >= 0) && (xx < WW);
                cw[threadIdx.x][cr] = v ? wgt[cr] * mask : 0.f;
                ci[threadIdx.x][cr] = v ? ((yy * WW + xx) * CIN + g * CG) : 0;
            }
        }
        __syncthreads();

        // phase A: build sampled tile [128c x 32pix] (coalesced 128B gathers)
        #pragma unroll
        for (int pj = 0; pj < 4; pj++) {
            int pl = wid + 8 * pj;
            float w0 = cw[pl][0], w1 = cw[pl][1], w2 = cw[pl][2], w3 = cw[pl][3];
            int   i0 = ci[pl][0], i1 = ci[pl][1], i2 = ci[pl][2], i3 = ci[pl][3];
            #pragma unroll
            for (int cj = 0; cj < 4; cj++) {
                int c = lane + 32 * cj;
                float v = w0 * xb[i0 + c] + w1 * xb[i1 + c]
                        + w2 * xb[i2 + c] + w3 * xb[i3 + c];
                s[c * 36 + pl] = v;
            }
        }
        __syncthreads();

        // phase B: register GEMM, f32x2-packed (16 fma2 per c per thread)
        const float4* wrow = (const float4*)&g_wt[(o * NTAP + tap) * CG];
        #pragma unroll 2
        for (int c4 = 0; c4 < 32; c4++) {
            float4 wv = wrow[c4];
            #pragma unroll
            for (int u = 0; u < 4; u++) {
                float wc = (&wv.x)[u];
                unsigned long long wp = pack2(wc, wc);
                const ulonglong2* srow = (const ulonglong2*)&s[(c4 * 4 + u) * 36];
                #pragma unroll
                for (int j2 = 0; j2 < 8; j2++) {
                    ulonglong2 sv = srow[j2];
                    acc[2 * j2]     = ffma2(sv.x, wp, acc[2 * j2]);
                    acc[2 * j2 + 1] = ffma2(sv.y, wp, acc[2 * j2 + 1]);
                }
            }
        }
    }

    // epilogue: conv bias + BatchNorm(eval) + ReLU, folded per channel
    float scale = gamma[o] * rsqrtf(rvar[o] + 1e-5f);
    float shift = (bconv[o] - rmean[o]) * scale + beta[o];
    float4* orow = (float4*)&out[(b * COUT + o) * NPIX + p0];
    #pragma unroll
    for (int q = 0; q < 8; q++) {
        float v0, v1, v2, v3;
        unpack2(acc[2 * q],     v0, v1);
        unpack2(acc[2 * q + 1], v2, v3);
        float4 r;
        r.x = fmaxf(v0 * scale + shift, 0.f);
        r.y = fmaxf(v1 * scale + shift, 0.f);
        r.z = fmaxf(v2 * scale + shift, 0.f);
        r.w = fmaxf(v3 * scale + shift, 0.f);
        orow[q] = r;
    }
}

// ---------------- launch ----------------
extern "C" void kernel_launch(void* const* d_in, const int* in_sizes, int n_in,
                              void* d_out, int out_size) {
    const float* x     = (const float*)d_in[0];
    const float* w_off = (const float*)d_in[1];
    const float* b_off = (const float*)d_in[2];
    const float* w     = (const float*)d_in[3];
    const float* bconv = (const float*)d_in[4];
    const float* gamma = (const float*)d_in[5];
    const float* beta  = (const float*)d_in[6];
    const float* rmean = (const float*)d_in[7];
    const float* rvar  = (const float*)d_in[8];
    float* out = (float*)d_out;

    k_transpose_x<<<dim3(NPIX / 32, CIN / 32, BB), dim3(32, 8)>>>(x);
    k_transpose_w<<<(COUT * NTAP * CG + 255) / 256, 256>>>(w);
    k_transpose_woff<<<(KK2 * CIN * 56 + 255) / 256, 256>>>(w_off);
    k_offset_conv<<<BB * (NPIX / 128), 128>>>(b_off);
    k_main<<<BB * (NPIX / 32), 256>>>(bconv, gamma, beta, rmean, rvar, out);
}

// round 6
// speedup vs baseline: 2.2848x; 2.2848x over previous
#include <cuda_runtime.h>
#include <math.h>

#define CIN  256
#define COUT 256
#define HH   64
#define WW   64
#define BB   4
#define DGRP 2
#define CG   128
#define KK2  9
#define NTAP 18
#define NPIX 4096   // 64*64

// ---------------- scratch (device globals; no allocations allowed) ----------------
__device__ float g_xt[BB * NPIX * CIN];          // x transposed to [B][H*W][C]
__device__ float g_wt2[NTAP * CG * COUT];        // w  -> [tap][c][o]        (2.36 MB)
__device__ float g_wofft2[KK2 * CIN * 64];       // w_off -> [k2][c][oc pad64]
__device__ float g_om[BB * NPIX * 54];           // offset-conv output [b][p][54]

// ---------------- packed f32x2 helpers ----------------
static __device__ __forceinline__ unsigned long long pack2(float a, float b) {
    unsigned long long r;
    asm("mov.b64 %0, {%1, %2};" : "=l"(r) : "f"(a), "f"(b));
    return r;
}
static __device__ __forceinline__ void unpack2(unsigned long long v, float& a, float& b) {
    asm("mov.b64 {%0, %1}, %2;" : "=f"(a), "=f"(b) : "l"(v));
}
static __device__ __forceinline__ unsigned long long ffma2(
    unsigned long long a, unsigned long long b, unsigned long long c) {
    unsigned long long d;
    asm("fma.rn.f32x2 %0, %1, %2, %3;" : "=l"(d) : "l"(a), "l"(b), "l"(c));
    return d;
}

// ---------------- kernel 0: x [B,C,H,W] -> g_xt [B,HW,C] ----------------
__global__ void k_transpose_x(const float* __restrict__ x) {
    __shared__ float tile[32][33];
    int b  = blockIdx.z;
    int p0 = blockIdx.x * 32;
    int c0 = blockIdx.y * 32;
    #pragma unroll
    for (int k = 0; k < 32; k += 8) {
        int c = c0 + threadIdx.y + k;
        int p = p0 + threadIdx.x;
        tile[threadIdx.y + k][threadIdx.x] = x[(b * CIN + c) * NPIX + p];
    }
    __syncthreads();
    #pragma unroll
    for (int k = 0; k < 32; k += 8) {
        int p = p0 + threadIdx.y + k;
        int c = c0 + threadIdx.x;
        g_xt[(b * NPIX + p) * CIN + c] = tile[threadIdx.x][threadIdx.y + k];
    }
}

// ---------------- kernel 1: w [O,C,3,3] -> g_wt2 [tap][c][o] ----------------
__global__ void k_transpose_w(const float* __restrict__ w) {
    int tid = blockIdx.x * blockDim.x + threadIdx.x;
    if (tid >= NTAP * CG * COUT) return;
    int o   = tid & 255;
    int c   = (tid >> 8) & 127;
    int tap = tid >> 15;
    int g   = tap / KK2, k2 = tap % KK2;
    g_wt2[tid] = w[(o * CIN + g * CG + c) * KK2 + k2];
}

// ---------------- kernel 2: w_off [54,C,3,3] -> g_wofft2 [k2][c][oc pad 64] ----------------
__global__ void k_transpose_woff(const float* __restrict__ w_off) {
    int tid = blockIdx.x * blockDim.x + threadIdx.x;
    if (tid >= KK2 * CIN * 64) return;
    int oc = tid & 63;
    int c  = (tid >> 6) & 255;
    int k2 = tid >> 14;
    g_wofft2[tid] = (oc < 54) ? w_off[(oc * CIN + c) * KK2 + k2] : 0.f;
}

// ---------------- kernel 3: offset conv ----------------
// block = 256 threads, tile = 64 oc(pad) x 64 pixels (one image row)
// thread = 4 oc (oq) x 4 pixels (pg); per tap stage x-tile [128c][64pix] in smem, 2 c-halves
__global__ void __launch_bounds__(256, 2) k_offset_conv(const float* __restrict__ b_off) {
    __shared__ __align__(16) float s[128 * 68];
    int b   = blockIdx.x >> 6;
    int row = blockIdx.x & 63;
    int p0  = row << 6;
    int oq  = threadIdx.x & 15;     // 16 oc-quads -> 64 oc
    int pg  = threadIdx.x >> 4;     // 16 pixel groups of 4
    int lane = threadIdx.x & 31, wid = threadIdx.x >> 5;
    const float* xb = &g_xt[(size_t)b * NPIX * CIN];

    unsigned long long acc[4][2];
    #pragma unroll
    for (int u = 0; u < 4; u++) { acc[u][0] = 0ull; acc[u][1] = 0ull; }

    for (int k2 = 0; k2 < KK2; k2++) {
        int ky = k2 / 3 - 1, kx = k2 % 3 - 1;
        int y = row + ky;
        bool yok = (y >= 0) && (y < HH);
        for (int ch = 0; ch < 2; ch++) {
            __syncthreads();
            // stage shifted x row, coalesced LDG, scatter STS (pitch 68)
            #pragma unroll
            for (int pj = 0; pj < 8; pj++) {
                int pl = wid + 8 * pj;
                int x_ = pl + kx;
                bool ok = yok && (x_ >= 0) && (x_ < WW);
                const float* src = &xb[((size_t)(y * WW + x_)) * CIN + ch * 128];
                #pragma unroll
                for (int cj = 0; cj < 4; cj++) {
                    int c = lane + 32 * cj;
                    s[c * 68 + pl] = ok ? src[c] : 0.f;
                }
            }
            __syncthreads();
            const float4* wk = (const float4*)g_wofft2 + (size_t)(k2 * CIN + ch * 128) * 16;
            #pragma unroll 8
            for (int c = 0; c < 128; c++) {
                float4 wv = wk[c * 16 + oq];
                unsigned long long wp0 = pack2(wv.x, wv.x);
                unsigned long long wp1 = pack2(wv.y, wv.y);
                unsigned long long wp2 = pack2(wv.z, wv.z);
                unsigned long long wp3 = pack2(wv.w, wv.w);
                ulonglong2 sv = *(const ulonglong2*)&s[c * 68 + pg * 4];
                acc[0][0] = ffma2(sv.x, wp0, acc[0][0]);
                acc[0][1] = ffma2(sv.y, wp0, acc[0][1]);
                acc[1][0] = ffma2(sv.x, wp1, acc[1][0]);
                acc[1][1] = ffma2(sv.y, wp1, acc[1][1]);
                acc[2][0] = ffma2(sv.x, wp2, acc[2][0]);
                acc[2][1] = ffma2(sv.y, wp2, acc[2][1]);
                acc[3][0] = ffma2(sv.x, wp3, acc[3][0]);
                acc[3][1] = ffma2(sv.y, wp3, acc[3][1]);
            }
        }
    }
    // store [b][pix][54] with bias
    float* omrow = &g_om[((size_t)b * NPIX + p0 + pg * 4) * 54];
    #pragma unroll
    for (int u = 0; u < 4; u++) {
        int oc = oq * 4 + u;
        if (oc < 54) {
            float bo = b_off[oc];
            #pragma unroll
            for (int jp = 0; jp < 2; jp++) {
                float v0, v1;
                unpack2(acc[u][jp], v0, v1);
                omrow[(jp * 2)     * 54 + oc] = v0 + bo;
                omrow[(jp * 2 + 1) * 54 + oc] = v1 + bo;
            }
        }
    }
}

// ---------------- kernel 4: deformable conv + BN + ReLU ----------------
// block = 256 threads, tile = 256 o x 64 pixels (one image row)
// thread = 4 o (oq) x 16 pixels (pg); per tap stage bilinear-sampled [128c][64pix]
__global__ void __launch_bounds__(256, 2) k_main(
    const float* __restrict__ bconv, const float* __restrict__ gamma,
    const float* __restrict__ beta,  const float* __restrict__ rmean,
    const float* __restrict__ rvar,  float* __restrict__ out) {

    __shared__ __align__(16) float s[128 * 68];
    __shared__ float cw[64][4];
    __shared__ int   ci[64][4];

    int b   = blockIdx.x >> 6;
    int row = blockIdx.x & 63;
    int p0  = row << 6;
    int oq  = threadIdx.x & 63;     // 64 o-quads -> 256 o
    int pg  = threadIdx.x >> 6;     // 4 pixel groups of 16
    int lane = threadIdx.x & 31, wid = threadIdx.x >> 5;

    unsigned long long acc[4][8];
    #pragma unroll
    for (int u = 0; u < 4; u++)
        #pragma unroll
        for (int j = 0; j < 8; j++) acc[u][j] = 0ull;

    const float* xb  = &g_xt[(size_t)b * NPIX * CIN];
    const float* omb = &g_om[(size_t)b * NPIX * 54];

    for (int tap = 0; tap < NTAP; tap++) {
        int g = tap / KK2, k2 = tap % KK2;
        __syncthreads();                 // prev phase B done before cw/s rewrite
        if (threadIdx.x < 64) {
            int p = p0 + threadIdx.x;
            int wx = threadIdx.x;
            const float* om = &omb[(size_t)p * 54 + tap];
            float offy = om[0], offx = om[18], mraw = om[36];
            float mask = 1.f / (1.f + expf(-mraw));
            float py = (float)(row + k2 / 3 - 1) + offy;
            float px = (float)(wx  + k2 % 3 - 1) + offx;
            float fy = floorf(py), fx = floorf(px);
            float ly = py - fy, lx = px - fx;
            int y0 = (int)fy, x0 = (int)fx;
            float wgt[4] = { (1.f - ly) * (1.f - lx), (1.f - ly) * lx,
                             ly * (1.f - lx),         ly * lx };
            #pragma unroll
            for (int cr = 0; cr < 4; cr++) {
                int yy = y0 + (cr >> 1), xx = x0 + (cr & 1);
                bool v = (yy >= 0) && (yy < HH) && (xx >= 0) && (xx < WW);
                cw[threadIdx.x][cr] = v ? wgt[cr] * mask : 0.f;
                ci[threadIdx.x][cr] = v ? ((yy * WW + xx) * CIN + g * CG) : 0;
            }
        }
        __syncthreads();

        // phase A: bilinear-sample tile [128c][64pix], coalesced 128B gathers
        #pragma unroll
        for (int pj = 0; pj < 8; pj++) {
            int pl = wid + 8 * pj;
            float w0 = cw[pl][0], w1 = cw[pl][1], w2 = cw[pl][2], w3 = cw[pl][3];
            int   i0 = ci[pl][0], i1 = ci[pl][1], i2 = ci[pl][2], i3 = ci[pl][3];
            #pragma unroll
            for (int cj = 0; cj < 4; cj++) {
                int c = lane + 32 * cj;
                float v = w0 * xb[i0 + c] + w1 * xb[i1 + c]
                        + w2 * xb[i2 + c] + w3 * xb[i3 + c];
                s[c * 68 + pl] = v;
            }
        }
        __syncthreads();

        // phase B: register GEMM, 4 o x 16 pix per thread
        const float4* wtap = (const float4*)g_wt2 + (size_t)tap * CG * 64;
        #pragma unroll 4
        for (int c = 0; c < 128; c++) {
            float4 wv = wtap[c * 64 + oq];
            unsigned long long wp0 = pack2(wv.x, wv.x);
            unsigned long long wp1 = pack2(wv.y, wv.y);
            unsigned long long wp2 = pack2(wv.z, wv.z);
            unsigned long long wp3 = pack2(wv.w, wv.w);
            const ulonglong2* srow = (const ulonglong2*)&s[c * 68 + pg * 16];
            ulonglong2 sa = srow[0], sb = srow[1], sc = srow[2], sd = srow[3];
            unsigned long long sv[8] = { sa.x, sa.y, sb.x, sb.y, sc.x, sc.y, sd.x, sd.y };
            #pragma unroll
            for (int j = 0; j < 8; j++) {
                acc[0][j] = ffma2(sv[j], wp0, acc[0][j]);
                acc[1][j] = ffma2(sv[j], wp1, acc[1][j]);
                acc[2][j] = ffma2(sv[j], wp2, acc[2][j]);
                acc[3][j] = ffma2(sv[j], wp3, acc[3][j]);
            }
        }
    }

    // epilogue: bias + BN(eval) + ReLU
    #pragma unroll
    for (int oo = 0; oo < 4; oo++) {
        int o = oq * 4 + oo;
        float scale = gamma[o] * rsqrtf(rvar[o] + 1e-5f);
        float shift = (bconv[o] - rmean[o]) * scale + beta[o];
        float2* orow = (float2*)&out[((size_t)(b * COUT + o)) * NPIX + p0 + pg * 16];
        #pragma unroll
        for (int j = 0; j < 8; j++) {
            float v0, v1;
            unpack2(acc[oo][j], v0, v1);
            float2 r;
            r.x = fmaxf(v0 * scale + shift, 0.f);
            r.y = fmaxf(v1 * scale + shift, 0.f);
            orow[j] = r;
        }
    }
}

// ---------------- launch ----------------
extern "C" void kernel_launch(void* const* d_in, const int* in_sizes, int n_in,
                              void* d_out, int out_size) {
    const float* x     = (const float*)d_in[0];
    const float* w_off = (const float*)d_in[1];
    const float* b_off = (const float*)d_in[2];
    const float* w     = (const float*)d_in[3];
    const float* bconv = (const float*)d_in[4];
    const float* gamma = (const float*)d_in[5];
    const float* beta  = (const float*)d_in[6];
    const float* rmean = (const float*)d_in[7];
    const float* rvar  = (const float*)d_in[8];
    float* out = (float*)d_out;

    k_transpose_x<<<dim3(NPIX / 32, CIN / 32, BB), dim3(32, 8)>>>(x);
    k_transpose_w<<<(NTAP * CG * COUT + 255) / 256, 256>>>(w);
    k_transpose_woff<<<(KK2 * CIN * 64 + 255) / 256, 256>>>(w_off);
    k_offset_conv<<<BB * 64, 256>>>(b_off);
    k_main<<<BB * 64, 256>>>(bconv, gamma, beta, rmean, rvar, out);
}

// round 10
// speedup vs baseline: 3.7569x; 1.6443x over previous
#include <cuda_runtime.h>
#include <math.h>
#include <stdint.h>

#define CIN  256
#define COUT 256
#define HH   64
#define WW   64
#define BB   4
#define DGRP 2
#define CG   128
#define KK2  9
#define NTAP 18
#define NPIX 4096   // 64*64

// ---------------- scratch (device globals; no allocations allowed) ----------------
__device__ float g_xt[BB * NPIX * CIN];                       // x -> [B][H*W][C]
__device__ float g_wofft2[KK2 * CIN * 64];                    // w_off -> [k2][c][oc pad64]
__device__ float g_om[BB * NPIX * 54];                        // offset-conv out [b][p][54]
__device__ __align__(128) unsigned char g_wbf[NTAP * 131072]; // per tap: [hi 64KB][lo 64KB], smem-final swizzled

// ---------------- packed f32x2 helpers (offset conv) ----------------
static __device__ __forceinline__ unsigned long long pack2(float a, float b) {
    unsigned long long r;
    asm("mov.b64 %0, {%1, %2};" : "=l"(r) : "f"(a), "f"(b));
    return r;
}
static __device__ __forceinline__ void unpack2(unsigned long long v, float& a, float& b) {
    asm("mov.b64 {%0, %1}, %2;" : "=f"(a), "=f"(b) : "l"(v));
}
static __device__ __forceinline__ unsigned long long ffma2(
    unsigned long long a, unsigned long long b, unsigned long long c) {
    unsigned long long d;
    asm("fma.rn.f32x2 %0, %1, %2, %3;" : "=l"(d) : "l"(a), "l"(b), "l"(c));
    return d;
}

// ---------------- bf16 helpers ----------------
// packbf(vlo, vhi): vlo -> low 16 bits, vhi -> high 16 bits
static __device__ __forceinline__ uint32_t packbf(float vlo, float vhi) {
    uint32_t r;
    asm("cvt.rn.bf16x2.f32 %0, %1, %2;" : "=r"(r) : "f"(vhi), "f"(vlo));
    return r;
}
static __device__ __forceinline__ float bflo(uint32_t w) { return __uint_as_float(w << 16); }
static __device__ __forceinline__ float bfhi(uint32_t w) { return __uint_as_float(w & 0xffff0000u); }

static __device__ __forceinline__ uint32_t smem_u32(const void* p) {
    uint32_t a;
    asm("{ .reg .u64 t; cvta.to.shared.u64 t, %1; cvt.u32.u64 %0, t; }" : "=r"(a) : "l"(p));
    return a;
}

// ---------------- mma.sync / ldmatrix (base-arch PTX, runs on HMMA pipe) ----------------
static __device__ __forceinline__ void ldsm4(uint32_t& r0, uint32_t& r1,
                                             uint32_t& r2, uint32_t& r3, uint32_t a) {
    asm volatile("ldmatrix.sync.aligned.m8n8.x4.shared.b16 {%0,%1,%2,%3}, [%4];"
                 : "=r"(r0), "=r"(r1), "=r"(r2), "=r"(r3) : "r"(a));
}
static __device__ __forceinline__ void mma16816(float* c, const uint32_t* a,
                                                uint32_t b0, uint32_t b1) {
    asm volatile(
        "mma.sync.aligned.m16n8k16.row.col.f32.bf16.bf16.f32 "
        "{%0,%1,%2,%3}, {%4,%5,%6,%7}, {%8,%9}, {%0,%1,%2,%3};"
        : "+f"(c[0]), "+f"(c[1]), "+f"(c[2]), "+f"(c[3])
        : "r"(a[0]), "r"(a[1]), "r"(a[2]), "r"(a[3]), "r"(b0), "r"(b1));
}

// smem tile addressing: rows of 128 bf16 (256B pitch), 16B-unit XOR swizzle by (row&7)
// byte(row, cbyte) = row*256 + (cbyte ^ ((row&7)<<4))

// ---------------- kernel 0: x [B,C,H,W] -> g_xt [B,HW,C] ----------------
__global__ void k_transpose_x(const float* __restrict__ x) {
    __shared__ float tile[32][33];
    int b  = blockIdx.z;
    int p0 = blockIdx.x * 32;
    int c0 = blockIdx.y * 32;
    #pragma unroll
    for (int k = 0; k < 32; k += 8)
        tile[threadIdx.y + k][threadIdx.x] = x[(b * CIN + c0 + threadIdx.y + k) * NPIX + p0 + threadIdx.x];
    __syncthreads();
    #pragma unroll
    for (int k = 0; k < 32; k += 8)
        g_xt[(b * NPIX + p0 + threadIdx.y + k) * CIN + c0 + threadIdx.x] = tile[threadIdx.x][threadIdx.y + k];
}

// ---------------- kernel 1: w -> g_wbf (bf16 hi/lo, swizzled [o row][c] tiles) ----------------
__global__ void k_prep_wbf(const float* __restrict__ w) {
    int tid = blockIdx.x * blockDim.x + threadIdx.x;
    if (tid >= NTAP * 256 * 64) return;
    int cp  = tid & 63;             // c pair index: c0 = 2*cp
    int o   = (tid >> 6) & 255;
    int tap = tid >> 14;
    int g = tap / KK2, k2 = tap % KK2;
    int c0 = cp * 2;
    float f0 = w[((size_t)o * CIN + g * CG + c0) * KK2 + k2];
    float f1 = w[((size_t)o * CIN + g * CG + c0 + 1) * KK2 + k2];
    uint32_t hiw = packbf(f0, f1);
    float r0 = f0 - bflo(hiw);
    float r1 = f1 - bfhi(hiw);
    uint32_t low = packbf(r0, r1);
    uint32_t sw = (uint32_t)o * 256 + (((uint32_t)c0 * 2) ^ (((uint32_t)(o & 7)) << 4));
    size_t base = (size_t)tap * 131072;
    *(uint32_t*)(g_wbf + base + sw)         = hiw;
    *(uint32_t*)(g_wbf + base + 65536 + sw) = low;
}

// ---------------- kernel 2: w_off -> g_wofft2 [k2][c][oc pad 64] ----------------
__global__ void k_transpose_woff(const float* __restrict__ w_off) {
    int tid = blockIdx.x * blockDim.x + threadIdx.x;
    if (tid >= KK2 * CIN * 64) return;
    int oc = tid & 63;
    int c  = (tid >> 6) & 255;
    int k2 = tid >> 14;
    g_wofft2[tid] = (oc < 54) ? w_off[(oc * CIN + c) * KK2 + k2] : 0.f;
}

// ---------------- kernel 3: offset conv (FFMA f32x2 path, unchanged) ----------------
__global__ void __launch_bounds__(256, 2) k_offset_conv(const float* __restrict__ b_off) {
    __shared__ __align__(16) float s[128 * 68];
    int b   = blockIdx.x >> 6;
    int row = blockIdx.x & 63;
    int p0  = row << 6;
    int oq  = threadIdx.x & 15;
    int pg  = threadIdx.x >> 4;
    int lane = threadIdx.x & 31, wid = threadIdx.x >> 5;
    const float* xb = &g_xt[(size_t)b * NPIX * CIN];

    unsigned long long acc[4][2];
    #pragma unroll
    for (int u = 0; u < 4; u++) { acc[u][0] = 0ull; acc[u][1] = 0ull; }

    for (int k2 = 0; k2 < KK2; k2++) {
        int ky = k2 / 3 - 1, kx = k2 % 3 - 1;
        int y = row + ky;
        bool yok = (y >= 0) && (y < HH);
        for (int ch = 0; ch < 2; ch++) {
            __syncthreads();
            #pragma unroll
            for (int pj = 0; pj < 8; pj++) {
                int pl = wid + 8 * pj;
                int x_ = pl + kx;
                bool ok = yok && (x_ >= 0) && (x_ < WW);
                const float* src = &xb[((size_t)(y * WW + x_)) * CIN + ch * 128];
                #pragma unroll
                for (int cj = 0; cj < 4; cj++) {
                    int c = lane + 32 * cj;
                    s[c * 68 + pl] = ok ? src[c] : 0.f;
                }
            }
            __syncthreads();
            const float4* wk = (const float4*)g_wofft2 + (size_t)(k2 * CIN + ch * 128) * 16;
            #pragma unroll 8
            for (int c = 0; c < 128; c++) {
                float4 wv = wk[c * 16 + oq];
                unsigned long long wp0 = pack2(wv.x, wv.x);
                unsigned long long wp1 = pack2(wv.y, wv.y);
                unsigned long long wp2 = pack2(wv.z, wv.z);
                unsigned long long wp3 = pack2(wv.w, wv.w);
                ulonglong2 sv = *(const ulonglong2*)&s[c * 68 + pg * 4];
                acc[0][0] = ffma2(sv.x, wp0, acc[0][0]);
                acc[0][1] = ffma2(sv.y, wp0, acc[0][1]);
                acc[1][0] = ffma2(sv.x, wp1, acc[1][0]);
                acc[1][1] = ffma2(sv.y, wp1, acc[1][1]);
                acc[2][0] = ffma2(sv.x, wp2, acc[2][0]);
                acc[2][1] = ffma2(sv.y, wp2, acc[2][1]);
                acc[3][0] = ffma2(sv.x, wp3, acc[3][0]);
                acc[3][1] = ffma2(sv.y, wp3, acc[3][1]);
            }
        }
    }
    float* omrow = &g_om[((size_t)b * NPIX + p0 + pg * 4) * 54];
    #pragma unroll
    for (int u = 0; u < 4; u++) {
        int oc = oq * 4 + u;
        if (oc < 54) {
            float bo = b_off[oc];
            #pragma unroll
            for (int jp = 0; jp < 2; jp++) {
                float v0, v1;
                unpack2(acc[u][jp], v0, v1);
                omrow[(jp * 2)     * 54 + oc] = v0 + bo;
                omrow[(jp * 2 + 1) * 54 + oc] = v1 + bo;
            }
        }
    }
}

// ---------------- kernel 4: deformable conv via mma.sync bf16x3 + BN + ReLU ----------------
// block = 256 thr (8 warps), tile = 128 pix x 256 o; warp tile = 64 pix x 64 o
// smem layout (dynamic):
#define SA_HI   0          // A hi tile 32KB: 128 pix rows x 128 c bf16, swizzled
#define SA_LO   32768      // A lo tile 32KB
#define SB_HI   65536      // B hi tile 64KB: 256 o rows x 128 c bf16, swizzled
#define SB_LO   131072     // B lo tile 64KB
#define SCW     196608     // float cw[128][4]
#define SCI     198656     // int   ci[128][4]
#define SSS     200704     // float scale[256]
#define SSH     201728     // float shift[256]
#define SMEM_SZ 202752

__global__ void __launch_bounds__(256, 1) k_main_mma(
    const float* __restrict__ bconv, const float* __restrict__ gamma,
    const float* __restrict__ beta,  const float* __restrict__ rmean,
    const float* __restrict__ rvar,  float* __restrict__ out) {

    extern __shared__ char dsm[];
    uint32_t sb = smem_u32(dsm);
    int tid = threadIdx.x;
    int lane = tid & 31, wid = tid >> 5;

    int b  = blockIdx.x >> 5;
    int p0 = (blockIdx.x & 31) << 7;     // 128 pixels (2 image rows)

    // warp tile origin
    int pix0 = (wid & 1) * 64;
    int o0   = (wid >> 1) * 64;

    float* cw  = (float*)(dsm + SCW);
    int*   ci  = (int*)(dsm + SCI);
    float* sss = (float*)(dsm + SSS);
    float* ssh = (float*)(dsm + SSH);

    {   // BN fold
        int o = tid;
        float sc = gamma[o] * rsqrtf(rvar[o] + 1e-5f);
        sss[o] = sc;
        ssh[o] = (bconv[o] - rmean[o]) * sc + beta[o];
    }

    // ldmatrix lane geometry (constant per thread)
    int rowA = lane & 15;                       // A: rows m0..m0+15
    uint32_t cA   = (uint32_t)((lane >> 4) << 4);        // 0 / 16
    int rowB = (lane & 7) + ((lane >> 4) << 3);          // B: n rows 0..15
    uint32_t cB   = (uint32_t)(((lane >> 3) & 1) << 4);  // 0 / 16 (per 8-lane group)
    uint32_t swz  = (uint32_t)((lane & 7) << 4);         // row&7 swizzle (same for A and B)

    uint32_t aRow[4], bRow[4];
    #pragma unroll
    for (int mt = 0; mt < 4; mt++)
        aRow[mt] = sb + SA_HI + (uint32_t)(pix0 + mt * 16 + rowA) * 256;
    #pragma unroll
    for (int ng = 0; ng < 4; ng++)
        bRow[ng] = sb + SB_HI + (uint32_t)(o0 + ng * 16 + rowB) * 256;

    float acc[4][8][4];
    #pragma unroll
    for (int mt = 0; mt < 4; mt++)
        #pragma unroll
        for (int nt = 0; nt < 8; nt++)
            #pragma unroll
            for (int q = 0; q < 4; q++) acc[mt][nt][q] = 0.f;

    const float* xb  = g_xt + (size_t)b * NPIX * CIN;
    const float* omb = g_om + (size_t)b * NPIX * 54;

    #pragma unroll 1
    for (int tap = 0; tap < NTAP; tap++) {
        int g = tap / KK2, k2 = tap % KK2;

        __syncthreads();   // everyone done reading previous A/B tiles

        // async flat copy of this tap's pre-swizzled B hi+lo (128KB)
        {
            const char* src = (const char*)g_wbf + (size_t)tap * 131072;
            #pragma unroll 4
            for (int i = tid; i < 8192; i += 256) {
                uint32_t dst = sb + SB_HI + (uint32_t)i * 16;
                asm volatile("cp.async.cg.shared.global [%0], [%1], 16;"
                             :: "r"(dst), "l"(src + (size_t)i * 16) : "memory");
            }
            asm volatile("cp.async.commit_group;" ::: "memory");
        }

        // offsets / bilinear corner weights for the 128 pixels
        if (tid < 128) {
            int p = p0 + tid;
            int prow = p >> 6, wx = p & 63;
            const float* om = &omb[(size_t)p * 54 + tap];
            float offy = om[0], offx = om[18], mraw = om[36];
            float mask = 1.f / (1.f + expf(-mraw));
            float py = (float)(prow + k2 / 3 - 1) + offy;
            float px = (float)(wx   + k2 % 3 - 1) + offx;
            float fy = floorf(py), fx = floorf(px);
            float ly = py - fy, lx = px - fx;
            int y0 = (int)fy, x0 = (int)fx;
            float wgt[4] = { (1.f - ly) * (1.f - lx), (1.f - ly) * lx,
                             ly * (1.f - lx),         ly * lx };
            #pragma unroll
            for (int cr = 0; cr < 4; cr++) {
                int yy = y0 + (cr >> 1), xx = x0 + (cr & 1);
                bool v = (yy >= 0) && (yy < HH) && (xx >= 0) && (xx < WW);
                cw[tid * 4 + cr] = v ? wgt[cr] * mask : 0.f;
                ci[tid * 4 + cr] = v ? ((yy * WW + xx) * CIN + g * CG) : 0;
            }
        }
        __syncthreads();

        // build A hi/lo tiles: warp w -> pix rows wid*16 .. +15; lane covers 4 c via float4
        #pragma unroll 4
        for (int j = 0; j < 16; j++) {
            int pl = wid * 16 + j;
            float w0 = cw[pl * 4 + 0], w1 = cw[pl * 4 + 1];
            float w2 = cw[pl * 4 + 2], w3 = cw[pl * 4 + 3];
            int   i0 = ci[pl * 4 + 0], i1 = ci[pl * 4 + 1];
            int   i2 = ci[pl * 4 + 2], i3 = ci[pl * 4 + 3];
            int c4 = lane * 4;
            float4 a0 = *(const float4*)(xb + i0 + c4);
            float4 a1 = *(const float4*)(xb + i1 + c4);
            float4 a2 = *(const float4*)(xb + i2 + c4);
            float4 a3 = *(const float4*)(xb + i3 + c4);
            float v0 = w0 * a0.x + w1 * a1.x + w2 * a2.x + w3 * a3.x;
            float v1 = w0 * a0.y + w1 * a1.y + w2 * a2.y + w3 * a3.y;
            float v2 = w0 * a0.z + w1 * a1.z + w2 * a2.z + w3 * a3.z;
            float v3 = w0 * a0.w + w1 * a1.w + w2 * a2.w + w3 * a3.w;
            uint32_t h0 = packbf(v0, v1), h1 = packbf(v2, v3);
            uint32_t l0 = packbf(v0 - bflo(h0), v1 - bfhi(h0));
            uint32_t l1 = packbf(v2 - bflo(h1), v3 - bfhi(h1));
            uint32_t off = (uint32_t)pl * 256 + (((uint32_t)lane * 8) ^ ((uint32_t)(pl & 7) << 4));
            *(uint2*)(dsm + SA_HI + off) = make_uint2(h0, h1);
            *(uint2*)(dsm + SA_LO + off) = make_uint2(l0, l1);
        }

        asm volatile("cp.async.wait_group 0;" ::: "memory");
        __syncthreads();

        // MMA phase: 8 k-chunks x (4 m-tiles x 8 n-tiles) x 3 precision terms
        #pragma unroll 2
        for (int kc = 0; kc < 8; kc++) {
            uint32_t cb = (uint32_t)kc * 32;
            uint32_t colA = (cb + cA) ^ swz;
            uint32_t colB = (cb + cB) ^ swz;
            uint32_t aH[4][4], aL[4][4];
            #pragma unroll
            for (int mt = 0; mt < 4; mt++) {
                uint32_t ra = aRow[mt] + colA;
                ldsm4(aH[mt][0], aH[mt][1], aH[mt][2], aH[mt][3], ra);
                ldsm4(aL[mt][0], aL[mt][1], aL[mt][2], aL[mt][3], ra + 32768);
            }
            #pragma unroll
            for (int ng = 0; ng < 4; ng++) {
                uint32_t rb = bRow[ng] + colB;
                uint32_t bh0, bh1, bh2, bh3, bl0, bl1, bl2, bl3;
                ldsm4(bh0, bh1, bh2, bh3, rb);
                ldsm4(bl0, bl1, bl2, bl3, rb + 65536);
                #pragma unroll
                for (int mt = 0; mt < 4; mt++) {
                    mma16816(acc[mt][2 * ng],     aH[mt], bh0, bh1);
                    mma16816(acc[mt][2 * ng],     aH[mt], bl0, bl1);
                    mma16816(acc[mt][2 * ng],     aL[mt], bh0, bh1);
                    mma16816(acc[mt][2 * ng + 1], aH[mt], bh2, bh3);
                    mma16816(acc[mt][2 * ng + 1], aH[mt], bl2, bl3);
                    mma16816(acc[mt][2 * ng + 1], aL[mt], bh2, bh3);
                }
            }
        }
    }

    // epilogue: BN + ReLU, direct stores (8-lane x 4B coalesced chunks)
    {
        int prow = p0 + pix0 + (lane >> 2);
        int obase = o0 + (lane & 3) * 2;
        #pragma unroll
        for (int mt = 0; mt < 4; mt++) {
            #pragma unroll
            for (int nt = 0; nt < 8; nt++) {
                int o = obase + nt * 8;
                int p = prow + mt * 16;
                float s0 = sss[o],     h0 = ssh[o];
                float s1 = sss[o + 1], h1 = ssh[o + 1];
                float* base0 = out + ((size_t)(b * COUT + o)) * NPIX;
                float* base1 = out + ((size_t)(b * COUT + o + 1)) * NPIX;
                base0[p]     = fmaxf(acc[mt][nt][0] * s0 + h0, 0.f);
                base1[p]     = fmaxf(acc[mt][nt][1] * s1 + h1, 0.f);
                base0[p + 8] = fmaxf(acc[mt][nt][2] * s0 + h0, 0.f);
                base1[p + 8] = fmaxf(acc[mt][nt][3] * s1 + h1, 0.f);
            }
        }
    }
}

// ---------------- launch ----------------
extern "C" void kernel_launch(void* const* d_in, const int* in_sizes, int n_in,
                              void* d_out, int out_size) {
    const float* x     = (const float*)d_in[0];
    const float* w_off = (const float*)d_in[1];
    const float* b_off = (const float*)d_in[2];
    const float* w     = (const float*)d_in[3];
    const float* bconv = (const float*)d_in[4];
    const float* gamma = (const float*)d_in[5];
    const float* beta  = (const float*)d_in[6];
    const float* rmean = (const float*)d_in[7];
    const float* rvar  = (const float*)d_in[8];
    float* out = (float*)d_out;

    cudaFuncSetAttribute(k_main_mma, cudaFuncAttributeMaxDynamicSharedMemorySize, SMEM_SZ);

    k_transpose_x<<<dim3(NPIX / 32, CIN / 32, BB), dim3(32, 8)>>>(x);
    k_prep_wbf<<<(NTAP * 256 * 64 + 255) / 256, 256>>>(w);
    k_transpose_woff<<<(KK2 * CIN * 64 + 255) / 256, 256>>>(w_off);
    k_offset_conv<<<BB * 64, 256>>>(b_off);
    k_main_mma<<<BB * 32, 256, SMEM_SZ>>>(bconv, gamma, beta, rmean, rvar, out);
}

// round 12
// speedup vs baseline: 5.0343x; 1.3400x over previous
#include <cuda_runtime.h>
#include <math.h>
#include <stdint.h>

#define CIN  256
#define COUT 256
#define HH   64
#define WW   64
#define BB   4
#define DGRP 2
#define CG   128
#define KK2  9
#define NTAP 18
#define NPIX 4096   // 64*64

// ---------------- scratch (device globals; no allocations allowed) ----------------
__device__ float g_xt[BB * NPIX * CIN];                       // x -> [B][H*W][C]
__device__ float g_om[BB * NPIX * 54];                        // offset-conv out [b][p][54]
__device__ __align__(128) unsigned char g_wbf[NTAP * 131072]; // main w: per tap [hi 64KB][lo 64KB], swizzled
__device__ __align__(128) unsigned char g_woffbf[KK2 * 2 * 32768]; // w_off: per (k2,half) [hi 16KB][lo 16KB]

// ---------------- bf16 helpers ----------------
// packbf(vlo, vhi): vlo -> low 16 bits, vhi -> high 16 bits
static __device__ __forceinline__ uint32_t packbf(float vlo, float vhi) {
    uint32_t r;
    asm("cvt.rn.bf16x2.f32 %0, %1, %2;" : "=r"(r) : "f"(vhi), "f"(vlo));
    return r;
}
static __device__ __forceinline__ float bflo(uint32_t w) { return __uint_as_float(w << 16); }
static __device__ __forceinline__ float bfhi(uint32_t w) { return __uint_as_float(w & 0xffff0000u); }

static __device__ __forceinline__ uint32_t smem_u32(const void* p) {
    uint32_t a;
    asm("{ .reg .u64 t; cvta.to.shared.u64 t, %1; cvt.u32.u64 %0, t; }" : "=r"(a) : "l"(p));
    return a;
}

// ---------------- mma.sync / ldmatrix (base-arch PTX, HMMA pipe) ----------------
static __device__ __forceinline__ void ldsm4(uint32_t& r0, uint32_t& r1,
                                             uint32_t& r2, uint32_t& r3, uint32_t a) {
    asm volatile("ldmatrix.sync.aligned.m8n8.x4.shared.b16 {%0,%1,%2,%3}, [%4];"
                 : "=r"(r0), "=r"(r1), "=r"(r2), "=r"(r3) : "r"(a));
}
static __device__ __forceinline__ void mma16816(float* c, const uint32_t* a,
                                                uint32_t b0, uint32_t b1) {
    asm volatile(
        "mma.sync.aligned.m16n8k16.row.col.f32.bf16.bf16.f32 "
        "{%0,%1,%2,%3}, {%4,%5,%6,%7}, {%8,%9}, {%0,%1,%2,%3};"
        : "+f"(c[0]), "+f"(c[1]), "+f"(c[2]), "+f"(c[3])
        : "r"(a[0]), "r"(a[1]), "r"(a[2]), "r"(a[3]), "r"(b0), "r"(b1));
}

// smem tile addressing: rows of 128 bf16 (256B pitch), 16B-unit XOR swizzle by (row&7)
// byte(row, cbyte) = row*256 + (cbyte ^ ((row&7)<<4))

// ---------------- kernel 0: x [B,C,H,W] -> g_xt [B,HW,C] ----------------
__global__ void k_transpose_x(const float* __restrict__ x) {
    __shared__ float tile[32][33];
    int b  = blockIdx.z;
    int p0 = blockIdx.x * 32;
    int c0 = blockIdx.y * 32;
    #pragma unroll
    for (int k = 0; k < 32; k += 8)
        tile[threadIdx.y + k][threadIdx.x] = x[(b * CIN + c0 + threadIdx.y + k) * NPIX + p0 + threadIdx.x];
    __syncthreads();
    #pragma unroll
    for (int k = 0; k < 32; k += 8)
        g_xt[(b * NPIX + p0 + threadIdx.y + k) * CIN + c0 + threadIdx.x] = tile[threadIdx.x][threadIdx.y + k];
}

// ---------------- kernel 1: w -> g_wbf (bf16 hi/lo, swizzled [o row][c] tiles) ----------------
__global__ void k_prep_wbf(const float* __restrict__ w) {
    int tid = blockIdx.x * blockDim.x + threadIdx.x;
    if (tid >= NTAP * 256 * 64) return;
    int cp  = tid & 63;             // c pair index: c0 = 2*cp
    int o   = (tid >> 6) & 255;
    int tap = tid >> 14;
    int g = tap / KK2, k2 = tap % KK2;
    int c0 = cp * 2;
    float f0 = w[((size_t)o * CIN + g * CG + c0) * KK2 + k2];
    float f1 = w[((size_t)o * CIN + g * CG + c0 + 1) * KK2 + k2];
    uint32_t hiw = packbf(f0, f1);
    float r0 = f0 - bflo(hiw);
    float r1 = f1 - bfhi(hiw);
    uint32_t low = packbf(r0, r1);
    uint32_t sw = (uint32_t)o * 256 + (((uint32_t)c0 * 2) ^ (((uint32_t)(o & 7)) << 4));
    size_t base = (size_t)tap * 131072;
    *(uint32_t*)(g_wbf + base + sw)         = hiw;
    *(uint32_t*)(g_wbf + base + 65536 + sw) = low;
}

// ---------------- kernel 2: w_off -> g_woffbf bf16 hi/lo tiles [k2][half]: 64 oc x 128 c ----------------
__global__ void k_prep_woffbf(const float* __restrict__ w_off) {
    int tid = blockIdx.x * blockDim.x + threadIdx.x;
    if (tid >= KK2 * 2 * 64 * 64) return;
    int cp   = tid & 63;            // c pair: c0 = 2*cp within half
    int o    = (tid >> 6) & 63;     // oc row (pad >=54 with 0)
    int half = (tid >> 12) & 1;
    int k2   = tid >> 13;           // 0..8
    int c0 = cp * 2;
    float f0 = 0.f, f1 = 0.f;
    if (o < 54) {
        f0 = w_off[((size_t)o * CIN + half * 128 + c0) * KK2 + k2];
        f1 = w_off[((size_t)o * CIN + half * 128 + c0 + 1) * KK2 + k2];
    }
    uint32_t hiw = packbf(f0, f1);
    float r0 = f0 - bflo(hiw);
    float r1 = f1 - bfhi(hiw);
    uint32_t low = packbf(r0, r1);
    uint32_t sw = (uint32_t)o * 256 + (((uint32_t)c0 * 2) ^ (((uint32_t)(o & 7)) << 4));
    size_t base = (size_t)(k2 * 2 + half) * 32768;
    *(uint32_t*)(g_woffbf + base + sw)         = hiw;
    *(uint32_t*)(g_woffbf + base + 16384 + sw) = low;
}

// ---------------- kernel 3: offset conv via mma.sync bf16x3 ----------------
// block = 256 thr (8 warps), tile = 128 pix x 64 oc(pad); warp = 64 pix x 16 oc
// smem: A hi 32KB | A lo 32KB | B hi 16KB | B lo 16KB = 96KB
#define OA_HI 0
#define OA_LO 32768
#define OB_HI 65536
#define OB_LO 81920
#define OSMEM_SZ 98304

__global__ void __launch_bounds__(256, 1) k_offset_mma(const float* __restrict__ b_off) {
    extern __shared__ char dsm[];
    uint32_t sb = smem_u32(dsm);
    int tid = threadIdx.x;
    int lane = tid & 31, wid = tid >> 5;

    int b  = blockIdx.x >> 5;
    int p0 = (blockIdx.x & 31) << 7;    // 128 pixels (2 image rows)

    int pixhalf = wid & 1;              // 0/1 -> 64-pixel half
    int o0      = (wid >> 1) * 16;      // 16 oc per warp

    // ldmatrix lane geometry
    int rowA = lane & 15;
    uint32_t cA  = (uint32_t)((lane >> 4) << 4);
    int rowB = (lane & 7) + ((lane >> 4) << 3);
    uint32_t cB  = (uint32_t)(((lane >> 3) & 1) << 4);
    uint32_t swz = (uint32_t)((lane & 7) << 4);

    uint32_t aRow[4];
    #pragma unroll
    for (int mt = 0; mt < 4; mt++)
        aRow[mt] = sb + OA_HI + (uint32_t)(pixhalf * 64 + mt * 16 + rowA) * 256;
    uint32_t bRow = sb + OB_HI + (uint32_t)(o0 + rowB) * 256;

    float acc[4][2][4];
    #pragma unroll
    for (int mt = 0; mt < 4; mt++)
        #pragma unroll
        for (int nt = 0; nt < 2; nt++)
            #pragma unroll
            for (int q = 0; q < 4; q++) acc[mt][nt][q] = 0.f;

    const float* xb = g_xt + (size_t)b * NPIX * CIN;

    #pragma unroll 1
    for (int s = 0; s < 18; s++) {
        int k2 = s >> 1, half = s & 1;
        int ky = k2 / 3 - 1, kx = k2 % 3 - 1;

        __syncthreads();

        // async copy B hi+lo (32KB)
        {
            const char* src = (const char*)g_woffbf + (size_t)(k2 * 2 + half) * 32768;
            #pragma unroll
            for (int i = 0; i < 8; i++) {
                int e = tid + i * 256;
                uint32_t dst = sb + OB_HI + (uint32_t)e * 16;
                asm volatile("cp.async.cg.shared.global [%0], [%1], 16;"
                             :: "r"(dst), "l"(src + (size_t)e * 16) : "memory");
            }
            asm volatile("cp.async.commit_group;" ::: "memory");
        }

        // build A hi/lo: warp w -> pix rows wid*16..+15; shifted copy (zero pad)
        #pragma unroll 4
        for (int j = 0; j < 16; j++) {
            int pl = wid * 16 + j;
            int p = p0 + pl;
            int prow = p >> 6, wx = p & 63;
            int y = prow + ky, x_ = wx + kx;
            bool ok = (y >= 0) && (y < HH) && (x_ >= 0) && (x_ < WW);
            float4 a = make_float4(0.f, 0.f, 0.f, 0.f);
            if (ok) a = *(const float4*)(xb + ((size_t)(y * WW + x_)) * CIN + half * 128 + lane * 4);
            uint32_t h0 = packbf(a.x, a.y), h1 = packbf(a.z, a.w);
            uint32_t l0 = packbf(a.x - bflo(h0), a.y - bfhi(h0));
            uint32_t l1 = packbf(a.z - bflo(h1), a.w - bfhi(h1));
            uint32_t off = (uint32_t)pl * 256 + (((uint32_t)lane * 8) ^ ((uint32_t)(pl & 7) << 4));
            *(uint2*)(dsm + OA_HI + off) = make_uint2(h0, h1);
            *(uint2*)(dsm + OA_LO + off) = make_uint2(l0, l1);
        }

        asm volatile("cp.async.wait_group 0;" ::: "memory");
        __syncthreads();

        // MMA: 8 k-chunks x 4 m-tiles x 2 n-tiles x 3 terms
        #pragma unroll 2
        for (int kc = 0; kc < 8; kc++) {
            uint32_t cb = (uint32_t)kc * 32;
            uint32_t colA = (cb + cA) ^ swz;
            uint32_t colB = (cb + cB) ^ swz;
            uint32_t aH[4][4], aL[4][4];
            #pragma unroll
            for (int mt = 0; mt < 4; mt++) {
                uint32_t ra = aRow[mt] + colA;
                ldsm4(aH[mt][0], aH[mt][1], aH[mt][2], aH[mt][3], ra);
                ldsm4(aL[mt][0], aL[mt][1], aL[mt][2], aL[mt][3], ra + 32768);
            }
            uint32_t rb = bRow + colB;
            uint32_t bh0, bh1, bh2, bh3, bl0, bl1, bl2, bl3;
            ldsm4(bh0, bh1, bh2, bh3, rb);
            ldsm4(bl0, bl1, bl2, bl3, rb + 16384);
            #pragma unroll
            for (int mt = 0; mt < 4; mt++) {
                mma16816(acc[mt][0], aH[mt], bh0, bh1);
                mma16816(acc[mt][0], aH[mt], bl0, bl1);
                mma16816(acc[mt][0], aL[mt], bh0, bh1);
                mma16816(acc[mt][1], aH[mt], bh2, bh3);
                mma16816(acc[mt][1], aH[mt], bl2, bl3);
                mma16816(acc[mt][1], aL[mt], bh2, bh3);
            }
        }
    }

    // epilogue: + b_off, store g_om [b][p][54]
    {
        int prow = p0 + pixhalf * 64 + (lane >> 2);
        int obase = o0 + (lane & 3) * 2;
        #pragma unroll
        for (int mt = 0; mt < 4; mt++) {
            #pragma unroll
            for (int nt = 0; nt < 2; nt++) {
                int o = obase + nt * 8;
                int p = prow + mt * 16;
                float* r0 = &g_om[((size_t)(b * NPIX) + p) * 54];
                float* r1 = r0 + 8 * 54;
                if (o < 54) {
                    float bo = b_off[o];
                    r0[o] = acc[mt][nt][0] + bo;
                    r1[o] = acc[mt][nt][2] + bo;
                }
                if (o + 1 < 54) {
                    float bo = b_off[o + 1];
                    r0[o + 1] = acc[mt][nt][1] + bo;
                    r1[o + 1] = acc[mt][nt][3] + bo;
                }
            }
        }
    }
}

// ---------------- kernel 4: deformable conv via mma.sync bf16x3 + BN + ReLU ----------------
// block = 256 thr (8 warps), tile = 128 pix x 256 o; warp tile = 64 pix x 64 o
#define SA_HI   0          // A hi tile 32KB: 128 pix rows x 128 c bf16, swizzled
#define SA_LO   32768      // A lo tile 32KB
#define SB_HI   65536      // B hi tile 64KB: 256 o rows x 128 c bf16, swizzled
#define SB_LO   131072     // B lo tile 64KB
#define SCW     196608     // float cw[128][4]
#define SCI     198656     // int   ci[128][4]
#define SSS     200704     // float scale[256]
#define SSH     201728     // float shift[256]
#define SMEM_SZ 202752

__global__ void __launch_bounds__(256, 1) k_main_mma(
    const float* __restrict__ bconv, const float* __restrict__ gamma,
    const float* __restrict__ beta,  const float* __restrict__ rmean,
    const float* __restrict__ rvar,  float* __restrict__ out) {

    extern __shared__ char dsm[];
    uint32_t sb = smem_u32(dsm);
    int tid = threadIdx.x;
    int lane = tid & 31, wid = tid >> 5;

    int b  = blockIdx.x >> 5;
    int p0 = (blockIdx.x & 31) << 7;     // 128 pixels (2 image rows)

    int pix0 = (wid & 1) * 64;
    int o0   = (wid >> 1) * 64;

    float* cw  = (float*)(dsm + SCW);
    int*   ci  = (int*)(dsm + SCI);
    float* sss = (float*)(dsm + SSS);
    float* ssh = (float*)(dsm + SSH);

    {   // BN fold
        int o = tid;
        float sc = gamma[o] * rsqrtf(rvar[o] + 1e-5f);
        sss[o] = sc;
        ssh[o] = (bconv[o] - rmean[o]) * sc + beta[o];
    }

    int rowA = lane & 15;
    uint32_t cA   = (uint32_t)((lane >> 4) << 4);
    int rowB = (lane & 7) + ((lane >> 4) << 3);
    uint32_t cB   = (uint32_t)(((lane >> 3) & 1) << 4);
    uint32_t swz  = (uint32_t)((lane & 7) << 4);

    uint32_t aRow[4], bRow[4];
    #pragma unroll
    for (int mt = 0; mt < 4; mt++)
        aRow[mt] = sb + SA_HI + (uint32_t)(pix0 + mt * 16 + rowA) * 256;
    #pragma unroll
    for (int ng = 0; ng < 4; ng++)
        bRow[ng] = sb + SB_HI + (uint32_t)(o0 + ng * 16 + rowB) * 256;

    float acc[4][8][4];
    #pragma unroll
    for (int mt = 0; mt < 4; mt++)
        #pragma unroll
        for (int nt = 0; nt < 8; nt++)
            #pragma unroll
            for (int q = 0; q < 4; q++) acc[mt][nt][q] = 0.f;

    const float* xb  = g_xt + (size_t)b * NPIX * CIN;
    const float* omb = g_om + (size_t)b * NPIX * 54;

    #pragma unroll 1
    for (int tap = 0; tap < NTAP; tap++) {
        int g = tap / KK2, k2 = tap % KK2;

        __syncthreads();   // everyone done reading previous A/B tiles

        // async flat copy of this tap's pre-swizzled B hi+lo (128KB)
        {
            const char* src = (const char*)g_wbf + (size_t)tap * 131072;
            #pragma unroll 4
            for (int i = tid; i < 8192; i += 256) {
                uint32_t dst = sb + SB_HI + (uint32_t)i * 16;
                asm volatile("cp.async.cg.shared.global [%0], [%1], 16;"
                             :: "r"(dst), "l"(src + (size_t)i * 16) : "memory");
            }
            asm volatile("cp.async.commit_group;" ::: "memory");
        }

        // offsets / bilinear corner weights for the 128 pixels
        if (tid < 128) {
            int p = p0 + tid;
            int prow = p >> 6, wx = p & 63;
            const float* om = &omb[(size_t)p * 54 + tap];
            float offy = om[0], offx = om[18], mraw = om[36];
            float mask = 1.f / (1.f + expf(-mraw));
            float py = (float)(prow + k2 / 3 - 1) + offy;
            float px = (float)(wx   + k2 % 3 - 1) + offx;
            float fy = floorf(py), fx = floorf(px);
            float ly = py - fy, lx = px - fx;
            int y0 = (int)fy, x0 = (int)fx;
            float wgt[4] = { (1.f - ly) * (1.f - lx), (1.f - ly) * lx,
                             ly * (1.f - lx),         ly * lx };
            #pragma unroll
            for (int cr = 0; cr < 4; cr++) {
                int yy = y0 + (cr >> 1), xx = x0 + (cr & 1);
                bool v = (yy >= 0) && (yy < HH) && (xx >= 0) && (xx < WW);
                cw[tid * 4 + cr] = v ? wgt[cr] * mask : 0.f;
                ci[tid * 4 + cr] = v ? ((yy * WW + xx) * CIN + g * CG) : 0;
            }
        }
        __syncthreads();

        // build A hi/lo tiles
        #pragma unroll 4
        for (int j = 0; j < 16; j++) {
            int pl = wid * 16 + j;
            float w0 = cw[pl * 4 + 0], w1 = cw[pl * 4 + 1];
            float w2 = cw[pl * 4 + 2], w3 = cw[pl * 4 + 3];
            int   i0 = ci[pl * 4 + 0], i1 = ci[pl * 4 + 1];
            int   i2 = ci[pl * 4 + 2], i3 = ci[pl * 4 + 3];
            int c4 = lane * 4;
            float4 a0 = *(const float4*)(xb + i0 + c4);
            float4 a1 = *(const float4*)(xb + i1 + c4);
            float4 a2 = *(const float4*)(xb + i2 + c4);
            float4 a3 = *(const float4*)(xb + i3 + c4);
            float v0 = w0 * a0.x + w1 * a1.x + w2 * a2.x + w3 * a3.x;
            float v1 = w0 * a0.y + w1 * a1.y + w2 * a2.y + w3 * a3.y;
            float v2 = w0 * a0.z + w1 * a1.z + w2 * a2.z + w3 * a3.z;
            float v3 = w0 * a0.w + w1 * a1.w + w2 * a2.w + w3 * a3.w;
            uint32_t h0 = packbf(v0, v1), h1 = packbf(v2, v3);
            uint32_t l0 = packbf(v0 - bflo(h0), v1 - bfhi(h0));
            uint32_t l1 = packbf(v2 - bflo(h1), v3 - bfhi(h1));
            uint32_t off = (uint32_t)pl * 256 + (((uint32_t)lane * 8) ^ ((uint32_t)(pl & 7) << 4));
            *(uint2*)(dsm + SA_HI + off) = make_uint2(h0, h1);
            *(uint2*)(dsm + SA_LO + off) = make_uint2(l0, l1);
        }

        asm volatile("cp.async.wait_group 0;" ::: "memory");
        __syncthreads();

        // MMA phase: 8 k-chunks x (4 m-tiles x 8 n-tiles) x 3 precision terms
        #pragma unroll 2
        for (int kc = 0; kc < 8; kc++) {
            uint32_t cb = (uint32_t)kc * 32;
            uint32_t colA = (cb + cA) ^ swz;
            uint32_t colB = (cb + cB) ^ swz;
            uint32_t aH[4][4], aL[4][4];
            #pragma unroll
            for (int mt = 0; mt < 4; mt++) {
                uint32_t ra = aRow[mt] + colA;
                ldsm4(aH[mt][0], aH[mt][1], aH[mt][2], aH[mt][3], ra);
                ldsm4(aL[mt][0], aL[mt][1], aL[mt][2], aL[mt][3], ra + 32768);
            }
            #pragma unroll
            for (int ng = 0; ng < 4; ng++) {
                uint32_t rb = bRow[ng] + colB;
                uint32_t bh0, bh1, bh2, bh3, bl0, bl1, bl2, bl3;
                ldsm4(bh0, bh1, bh2, bh3, rb);
                ldsm4(bl0, bl1, bl2, bl3, rb + 65536);
                #pragma unroll
                for (int mt = 0; mt < 4; mt++) {
                    mma16816(acc[mt][2 * ng],     aH[mt], bh0, bh1);
                    mma16816(acc[mt][2 * ng],     aH[mt], bl0, bl1);
                    mma16816(acc[mt][2 * ng],     aL[mt], bh0, bh1);
                    mma16816(acc[mt][2 * ng + 1], aH[mt], bh2, bh3);
                    mma16816(acc[mt][2 * ng + 1], aH[mt], bl2, bl3);
                    mma16816(acc[mt][2 * ng + 1], aL[mt], bh2, bh3);
                }
            }
        }
    }

    // epilogue: BN + ReLU, direct stores
    {
        int prow = p0 + pix0 + (lane >> 2);
        int obase = o0 + (lane & 3) * 2;
        #pragma unroll
        for (int mt = 0; mt < 4; mt++) {
            #pragma unroll
            for (int nt = 0; nt < 8; nt++) {
                int o = obase + nt * 8;
                int p = prow + mt * 16;
                float s0 = sss[o],     h0 = ssh[o];
                float s1 = sss[o + 1], h1 = ssh[o + 1];
                float* base0 = out + ((size_t)(b * COUT + o)) * NPIX;
                float* base1 = out + ((size_t)(b * COUT + o + 1)) * NPIX;
                base0[p]     = fmaxf(acc[mt][nt][0] * s0 + h0, 0.f);
                base1[p]     = fmaxf(acc[mt][nt][1] * s1 + h1, 0.f);
                base0[p + 8] = fmaxf(acc[mt][nt][2] * s0 + h0, 0.f);
                base1[p + 8] = fmaxf(acc[mt][nt][3] * s1 + h1, 0.f);
            }
        }
    }
}

// ---------------- launch ----------------
extern "C" void kernel_launch(void* const* d_in, const int* in_sizes, int n_in,
                              void* d_out, int out_size) {
    const float* x     = (const float*)d_in[0];
    const float* w_off = (const float*)d_in[1];
    const float* b_off = (const float*)d_in[2];
    const float* w     = (const float*)d_in[3];
    const float* bconv = (const float*)d_in[4];
    const float* gamma = (const float*)d_in[5];
    const float* beta  = (const float*)d_in[6];
    const float* rmean = (const float*)d_in[7];
    const float* rvar  = (const float*)d_in[8];
    float* out = (float*)d_out;

    cudaFuncSetAttribute(k_main_mma,   cudaFuncAttributeMaxDynamicSharedMemorySize, SMEM_SZ);
    cudaFuncSetAttribute(k_offset_mma, cudaFuncAttributeMaxDynamicSharedMemorySize, OSMEM_SZ);

    k_transpose_x<<<dim3(NPIX / 32, CIN / 32, BB), dim3(32, 8)>>>(x);
    k_prep_wbf<<<(NTAP * 256 * 64 + 255) / 256, 256>>>(w);
    k_prep_woffbf<<<(KK2 * 2 * 64 * 64 + 255) / 256, 256>>>(w_off);
    k_offset_mma<<<BB * 32, 256, OSMEM_SZ>>>(b_off);
    k_main_mma<<<BB * 32, 256, SMEM_SZ>>>(bconv, gamma, beta, rmean, rvar, out);
}